// round 4
// baseline (speedup 1.0000x reference)
#include <cuda_runtime.h>

#define JNT 17
#define WIN 24
#define HT  48
#define WT_ 48
#define CHW 576   // 24*24

struct __align__(16) WTab { int k0, k1; float w0, w1; };

// jax.image.resize 'bilinear' 24->48 weights (edge-renormalized).
#define P2(k) {k,(k)+1,0.75f,0.25f},{k,(k)+1,0.25f,0.75f},
__constant__ WTab c_wt[48] = {
    {0, 0, 1.0f, 0.0f},
    P2(0)  P2(1)  P2(2)  P2(3)  P2(4)  P2(5)  P2(6)  P2(7)
    P2(8)  P2(9)  P2(10) P2(11) P2(12) P2(13) P2(14) P2(15)
    P2(16) P2(17) P2(18) P2(19) P2(20) P2(21) P2(22)
    {23, 23, 1.0f, 0.0f}
};

// 4-tap bilinear: H contracted first then W, fmaf(w1,v1, rn(w0*v0)) ordering —
// bit-identical to the reference resize at every pixel.
__device__ __forceinline__ float up_val(const float* __restrict__ p, WTab wy, WTab wx) {
    const float* r0 = p + wy.k0 * WIN;
    const float* r1 = p + wy.k1 * WIN;
    float v00 = __ldg(r0 + wx.k0);
    float v10 = __ldg(r1 + wx.k0);
    float v01 = __ldg(r0 + wx.k1);
    float v11 = __ldg(r1 + wx.k1);
    float a = fmaf(wy.w1, v10, __fmul_rn(wy.w0, v00));
    float b = fmaf(wy.w1, v11, __fmul_rn(wy.w0, v01));
    return fmaf(wx.w1, b, __fmul_rn(wx.w0, a));
}

// Exact reference formula: tmp = (hm_up / sqrt(d2 + 1e-9)) / 1.8
__device__ __forceinline__ float tmp_at(const float* __restrict__ hp,
                                        int iy, int ix, float rx, float ry) {
    WTab wy = c_wt[iy];
    WTab wx = c_wt[ix];
    float h  = up_val(hp, wy, wx);
    float dx = __fsub_rn((float)ix, rx);
    float dy = __fsub_rn((float)iy, ry);
    float d2 = __fadd_rn(__fmul_rn(dx, dx), __fmul_rn(dy, dy));
    float t  = __fadd_rn(d2, 1e-9f);
    float q  = __fdiv_rn(h, __fsqrt_rn(t));
    return __fdiv_rn(q, 1.8f);
}

__global__ void __launch_bounds__(192)
movenet_fused(const float* __restrict__ hm,
              const float* __restrict__ ct,
              const float* __restrict__ rg,
              const float* __restrict__ of,
              float* __restrict__ out) {
    int b    = blockIdx.x;
    int tid  = threadIdx.x;
    int warp = tid >> 5;
    int lane = tid & 31;

    __shared__ float hbuf[HT * WIN];          // H-upsampled ct: 48 x 24
    __shared__ float s_rx[JNT], s_ry[JNT];
    __shared__ float s_rv[6];
    __shared__ int   s_ri[6];

    const float* cp = ct + (size_t)b * CHW;

    // ---- Phase 1: H-pass. thread = (col c, 6-row strip s). 5 loads -> 6 rows,
    // immediate weights, bitwise identical to reference contraction. ----
    {
        int c = tid % WIN;          // lanes 0..23 consecutive cols -> coalesced
        int s = tid / WIN;          // 0..7
        const float* col = cp + c;
        int base = 3 * s;
        float rm1 = __ldg(col + max(base - 1, 0) * WIN);
        float r0  = __ldg(col + base * WIN);
        float r1  = __ldg(col + (base + 1) * WIN);
        float r2  = __ldg(col + (base + 2) * WIN);
        float r3  = __ldg(col + min(base + 3, 23) * WIN);
        float* hb = hbuf + 6 * s * WIN + c;
        hb[0 * WIN] = (s == 0) ? r0 : fmaf(0.75f, r0, __fmul_rn(0.25f, rm1));
        hb[1 * WIN] = fmaf(0.25f, r1, __fmul_rn(0.75f, r0));
        hb[2 * WIN] = fmaf(0.75f, r1, __fmul_rn(0.25f, r0));
        hb[3 * WIN] = fmaf(0.25f, r2, __fmul_rn(0.75f, r1));
        hb[4 * WIN] = fmaf(0.75f, r2, __fmul_rn(0.25f, r1));
        hb[5 * WIN] = (s == 7) ? r2 : fmaf(0.25f, r3, __fmul_rn(0.75f, r2));
    }
    __syncthreads();

    // ---- Phase 2: W-pass + argmax. thread = 12 consecutive px of one row.
    // 8 shared loads cover all taps; unrolled, immediate weights. ----
    int cy, cx;
    {
        int row = tid >> 2;                 // 0..47
        int q   = tid & 3;                  // 0..3
        const float* h = hbuf + row * WIN + 6 * q;
        float hv[8];
        hv[0] = (q > 0) ? h[-1] : h[0];     // tap k-1 of first even pixel
        #pragma unroll
        for (int j = 0; j < 6; j++) hv[1 + j] = h[j];
        hv[7] = (q < 3) ? h[6] : h[5];

        int idx0 = row * WT_ + q * 12;
        float bv = -1.0f;
        int   bi = 1 << 30;
        #pragma unroll
        for (int i = 0; i < 12; i++) {
            float v;
            if (i & 1) v = fmaf(0.25f, hv[1 + (i + 1) / 2], __fmul_rn(0.75f, hv[1 + (i - 1) / 2]));
            else       v = fmaf(0.75f, hv[1 + i / 2],       __fmul_rn(0.25f, hv[i / 2]));
            if (i == 0  && q == 0) v = hv[1];   // ix=0  -> exact edge tap
            if (i == 11 && q == 3) v = hv[6];   // ix=47 -> exact edge tap
            if (v > bv) { bv = v; bi = idx0 + i; }  // ascending idx: > keeps first
        }
        #pragma unroll
        for (int o = 16; o; o >>= 1) {
            float ov = __shfl_down_sync(0xffffffffu, bv, o);
            int   oi = __shfl_down_sync(0xffffffffu, bi, o);
            if (ov > bv || (ov == bv && oi < bi)) { bv = ov; bi = oi; }
        }
        if (lane == 0) { s_rv[warp] = bv; s_ri[warp] = bi; }
    }
    __syncthreads();

    {   // every thread resolves the block winner (no extra sync/broadcast)
        float v = s_rv[0]; int i = s_ri[0];
        #pragma unroll
        for (int w = 1; w < 6; w++)
            if (s_rv[w] > v || (s_rv[w] == v && s_ri[w] < i)) { v = s_rv[w]; i = s_ri[w]; }
        cy = i / WT_;
        cx = i - cy * WT_;
    }

    // ---- Phase 3: gather 34 reg channels at center, clip ----
    if (tid < 2 * JNT) {
        WTab wyc = c_wt[cy];
        WTab wxc = c_wt[cx];
        const float* rp = rg + ((size_t)b * (2 * JNT) + tid) * CHW;
        float v = up_val(rp, wyc, wxc);
        int j = tid >> 1;
        if (tid & 1) {
            float y = __fadd_rn(__fadd_rn((float)cy, v), 0.5f);
            s_ry[j] = fminf(fmaxf(y, 0.0f), (float)(HT - 1));
        } else {
            float x = __fadd_rn(__fadd_rn((float)cx, v), 0.5f);
            s_rx[j] = fminf(fmaxf(x, 0.0f), (float)(WT_ - 1));
        }
    }
    __syncthreads();

    // ---- Phase 4: joints, one warp per joint ----
    // (a) cheap approx scan of a 6x5 seed window picks a candidate pixel;
    // (b) ONE exact eval there gives a valid lower bound wv on the true max
    //     (any true tmp value is a lower bound, approx ordering errors don't
    //     matter);
    // (c) prune: tmp <= 1.0001/(1.8*d) since hm_up < 1 (+rounding slack), so
    //     pixels with d > r = 1.0001/(1.8*wv) strictly lose;
    // (d) exact argmax over the tiny surviving box (first-index tie-break).
    for (int j = warp; j < JNT; j += 6) {
        const float* hp = hm + ((size_t)b * JNT + j) * CHW;
        float rx = s_rx[j];
        float ry = s_ry[j];

        int cxw = __float2int_rn(rx);
        int cyw = __float2int_rn(ry);
        int wxs = min(max(cxw - 2, 0), WT_ - 6);
        int wys = min(max(cyw - 2, 0), HT - 5);

        // (a) approx scan: h * rsqrt(t) — ordering only, no exactness needed
        float av = -1.0f;
        int   ai = 0;
        if (lane < 30) {
            int oy = lane / 6;
            int ox = lane - oy * 6;
            int iy = wys + oy;
            int ix = wxs + ox;
            WTab wy = c_wt[iy];
            WTab wx = c_wt[ix];
            float h  = up_val(hp, wy, wx);
            float dx = (float)ix - rx;
            float dy = (float)iy - ry;
            float t  = dx * dx + dy * dy + 1e-9f;
            av = h * __frsqrt_rn(t);
            ai = iy * WT_ + ix;
        }
        #pragma unroll
        for (int o = 16; o; o >>= 1) {
            float ov = __shfl_xor_sync(0xffffffffu, av, o);
            int   oi = __shfl_xor_sync(0xffffffffu, ai, o);
            if (ov > av || (ov == av && oi < ai)) { av = ov; ai = oi; }
        }

        // (b) exact lower bound at the candidate (all lanes, same pixel)
        int biy = ai / WT_;
        int bix = ai - biy * WT_;
        float wv = tmp_at(hp, biy, bix, rx, ry);
        float r  = (wv > 0.0f) ? __fdiv_rn(1.0001f, __fmul_rn(1.8f, wv)) : 1e9f;

        // (c) surviving box (candidate pixel is provably inside it)
        int iy0 = max(0,        __float2int_ru(ry - r - 0.01f));
        int iy1 = min(HT - 1,   __float2int_rd(ry + r + 0.01f));
        int ix0 = max(0,        __float2int_ru(rx - r - 0.01f));
        int ix1 = min(WT_ - 1,  __float2int_rd(rx + r + 0.01f));

        // (d) exact argmax over the box
        float jv = -1.0f;
        int   ji = 1 << 30;
        int bw = ix1 - ix0 + 1;
        int n  = bw * (iy1 - iy0 + 1);
        int mrec = ((1 << 20) + bw - 1) / bw;   // exact t/bw for t<=2303, bw<=48
        for (int t = lane; t < n; t += 32) {
            int qq = (t * mrec) >> 20;
            int iy = iy0 + qq;
            int ix = ix0 + (t - qq * bw);
            float v = tmp_at(hp, iy, ix, rx, ry);
            int idx = iy * WT_ + ix;
            if (v > jv || (v == jv && idx < ji)) { jv = v; ji = idx; }
        }
        #pragma unroll
        for (int o = 16; o; o >>= 1) {
            float ov = __shfl_xor_sync(0xffffffffu, jv, o);
            int   oi = __shfl_xor_sync(0xffffffffu, ji, o);
            if (ov > jv || (ov == jv && oi < ji)) { jv = ov; ji = oi; }
        }

        int jy = ji / WT_;
        int jx = ji - jy * WT_;
        WTab wyj = c_wt[jy];
        WTab wxj = c_wt[jx];

        // epilogue spread over lanes 0..2: x, y, score
        if (lane < 3) {
            float res;
            if (lane == 2) {
                res = up_val(hp, wyj, wxj);                       // score
            } else {
                const float* op = of + ((size_t)b * (2 * JNT) + 2 * j + lane) * CHW;
                float offv = up_val(op, wyj, wxj);
                float base = (lane == 0) ? (float)jx : (float)jy;
                res = __fdiv_rn(__fadd_rn(base, offv), 48.0f);
            }
            out[(size_t)b * (3 * JNT) + 3 * j + lane] = res;
        }
    }
}

extern "C" void kernel_launch(void* const* d_in, const int* in_sizes, int n_in,
                              void* d_out, int out_size) {
    const float* hm = (const float*)d_in[0];
    const float* ct = (const float*)d_in[1];
    const float* rg = (const float*)d_in[2];
    const float* of = (const float*)d_in[3];
    float* out = (float*)d_out;

    int B = in_sizes[1] / CHW;   // ct is (B,1,24,24)
    movenet_fused<<<B, 192>>>(hm, ct, rg, of, out);
}